// round 15
// baseline (speedup 1.0000x reference)
#include <cuda_runtime.h>
#include <cuda_fp16.h>
#include <math.h>

#define NN      100000
#define NATOMS  100
#define NGRAPH  1000
#define DEG     20
#define H       32
#define EDIM    51
#define NCONV   3
#define GDIM    16
#define TBL     2048        // he(d) table intervals
#define PADA    104         // padded atom rows (tile 12 covers 96..103)
#define HP      (H / 2)     // 16 half2 per row

// dynamic smem layout (float4 arrays first for alignment)
// float4 weights: 3*256*16 = 12288 B
// s_emb: PADA*H*4 = 13312 B ; s_hh + s_ch: 2 * PADA*HP*4 = 13312 B
// bo1/bo2/coef/warp/pooled: (3*H + 8*H + H)*4 = 1536 B
#define SM_W4      (3 * 256)
#define SM_FLOATS  (PADA * H + 3 * H + 8 * H + H)
#define SM_UINTS   (2 * PADA * HP)
#define SMEM_BYTES (SM_W4 * 16 + SM_FLOATS * 4 + SM_UINTS * 4)

// ---- device scratch ----
__device__ float    g_raw[NCONV * (TBL + 1) * H];   // he at grid points (fp32)
__device__ uint2    g_tblh[NCONV * TBL * HP];       // per lane-pair: {half2 vals, half2 slopes}
__device__ unsigned g_edges[NN * DEG];              // packed (dst_local|i0|fr13)

__device__ __forceinline__ float tanh_fast(float x) {
    float e = __expf(-2.0f * fabsf(x));
    float t = (1.0f - e) / (1.0f + e);
    return copysignf(t, x);
}

__device__ __forceinline__ unsigned pack_h2(float x, float y) {
    __half2 h = __floats2half2_rn(x, y);
    return *(unsigned*)&h;
}
__device__ __forceinline__ float2 unpack_h2(unsigned u) {
    return __half22float2(*(__half2*)&u);
}
// load 4 consecutive half features as float4
__device__ __forceinline__ float4 ld_h4(const unsigned* p) {
    uint2 u = *(const uint2*)p;
    float2 a = unpack_h2(u.x);
    float2 b = unpack_h2(u.y);
    return make_float4(a.x, a.y, b.x, b.y);
}

// ============================================================
// Table build: he_l(d) at TBL+1 grid points.
// ============================================================
__global__ void build_raw_kernel(const float* __restrict__ Wf1,
                                 const float* __restrict__ bf1,
                                 const float* __restrict__ Wf2,
                                 const float* __restrict__ bf2) {
    const int l = blockIdx.y;
    __shared__ float s_Wf1[H * EDIM];
    __shared__ float s_Wf2T[H * H];
    __shared__ float s_bf1[H], s_bf2[H];
    __shared__ float s_ee[8][EDIM];
    __shared__ float s_f1[8][H];

    int tid = threadIdx.x;
    for (int i = tid; i < H * EDIM; i += blockDim.x)
        s_Wf1[i] = Wf1[l * H * EDIM + i];
    for (int i = tid; i < H * H; i += blockDim.x) {
        int k = i / H, m = i % H;
        s_Wf2T[m * H + k] = Wf2[l * H * H + i];
    }
    if (tid < H) { s_bf1[tid] = bf1[l * H + tid]; s_bf2[tid] = bf2[l * H + tid]; }
    __syncthreads();

    int w = tid >> 5, lane = tid & 31;
    int t = blockIdx.x * 8 + w;
    if (t > TBL) return;
    float d = (float)t * (10.0f / (float)TBL);

    for (int j = lane; j < EDIM; j += 32) {
        float dc = d - 0.2f * (float)j;
        s_ee[w][j] = __expf(-25.0f * dc * dc);
    }
    __syncwarp();

    float acc = s_bf1[lane];
    for (int j = 0; j < EDIM; j++)
        acc = fmaf(s_ee[w][j], s_Wf1[lane * EDIM + j], acc);
    s_f1[w][lane] = tanh_fast(acc);
    __syncwarp();

    float he = s_bf2[lane];
#pragma unroll
    for (int m = 0; m < H; m++)
        he = fmaf(s_f1[w][m], s_Wf2T[m * H + lane], he);
    g_raw[(l * (TBL + 1) + t) * H + lane] = he;
}

// pack half2 (vals, slopes) per feature pair
__global__ void pack_table_kernel() {
    int idx = blockIdx.x * blockDim.x + threadIdx.x;   // over NCONV*TBL*16
    if (idx >= NCONV * TBL * HP) return;
    int l  = idx / (TBL * HP);
    int r  = idx - l * (TBL * HP);
    int i  = r >> 4;            // interval
    int fp = r & 15;            // feature pair
    const float* r0 = g_raw + (l * (TBL + 1) + i) * H + 2 * fp;
    const float* r1 = r0 + H;
    float v0 = r0[0], v1 = r0[1];
    float s0 = r1[0] - v0, s1 = r1[1] - v1;
    uint2 e;
    e.x = pack_h2(v0, v1);
    e.y = pack_h2(s0, s1);
    g_tblh[idx] = e;
}

// ============================================================
// Edge pre-pack: bits [0:7) dst_local, [7:19) i0, [19:32) fr*8192
// ============================================================
__global__ void pack_edges_kernel(const float* __restrict__ data) {
    int e = blockIdx.x * blockDim.x + threadIdx.x;
    if (e >= NN * DEG) return;
    int src   = e / DEG;
    int base  = (src / NATOMS) * NATOMS;
    int dl    = (int)data[e * 3 + 1] - base;
    float u   = data[e * 3 + 2] * ((float)TBL * 0.1f);
    int i0    = min((int)u, TBL - 1);
    int fri   = min((int)((u - (float)i0) * 8192.0f), 8191);
    g_edges[e] = (unsigned)dl | ((unsigned)i0 << 7) | ((unsigned)fri << 19);
}

// ============================================================
// Fused 3-layer kernel: block per graph (dynamic smem).
// s_h / s_conv staged as half2 (halves B1 gather wavefronts and
// the smem footprint -> 5 blocks/SM). Matvec + edge structure
// identical to the 258us kernel.
// ============================================================
__global__ void __launch_bounds__(256, 5)
fused_kernel(const float* __restrict__ emb_table,
             const float* __restrict__ W_init,
             const float* __restrict__ coef,
             const float* __restrict__ Wo1, const float* __restrict__ bo1,
             const float* __restrict__ Wo2, const float* __restrict__ bo2,
             const float* __restrict__ Wg,  const float* __restrict__ bg,
             float* __restrict__ out) {
    extern __shared__ float4 smem4[];
    float4* s_Wi4  = smem4;            // 256 float4
    float4* s_Wo14 = smem4 + 256;
    float4* s_Wo24 = smem4 + 512;
    float*  fbase  = (float*)(smem4 + SM_W4);
    float*  s_emb  = fbase;                       // PADA*H
    float*  s_bo1  = s_emb  + PADA * H;           // H
    float*  s_bo2  = s_bo1  + H;                  // H
    float*  s_coef = s_bo2  + H;                  // H
    float*  s_warp = s_coef + H;                  // 8*H
    float*  s_pooled = s_warp + 8 * H;            // H
    unsigned* s_hh = (unsigned*)(s_pooled + H);   // PADA*HP (half2 h)
    unsigned* s_ch = s_hh + PADA * HP;            // PADA*HP (half2 conv/o1)

    const int tid  = threadIdx.x;
    const int w    = tid >> 5;
    const int lane = tid & 31;
    const int lh   = lane & 15;      // feature pair index
    const int hb   = lane & 16;      // half base
    const int half = hb >> 4;
    const int g    = blockIdx.x;
    const int base = g * NATOMS;
    const unsigned FULL = 0xffffffffu;

    // init embeddings; zero pad rows of all staging arrays
    for (int i = tid; i < NATOMS * H; i += 256) s_emb[i] = emb_table[i];
    for (int i = NATOMS * H + tid; i < PADA * H; i += 256) s_emb[i] = 0.f;
    for (int i = NATOMS * HP + tid; i < PADA * HP; i += 256) {
        s_hh[i] = 0u; s_ch[i] = 0u;
    }

    float2 pool = make_float2(0.f, 0.f);

    // weight-pack indices (one float4 per thread per matrix)
    const int pmq = tid >> 5;            // m-quad 0..7
    const int pj  = (tid >> 4) & 1;      // column parity
    const int pf  = tid & 15;            // feature pair
    const int pdst = (pmq * 2 + pj) * 16 + pf;
    const int psrc = (2 * pf + pj) * H + 4 * pmq;

    for (int l = 0; l < NCONV; l++) {
        // ---- pack weights as column quads ----
        s_Wi4 [pdst] = *(const float4*)&W_init[l * H * H + psrc];
        s_Wo14[pdst] = *(const float4*)&Wo1   [l * H * H + psrc];
        s_Wo24[pdst] = *(const float4*)&Wo2   [l * H * H + psrc];
        if (tid < H) {
            s_bo1[tid]  = bo1[l * H + tid];
            s_bo2[tid]  = bo2[l * H + tid];
            s_coef[tid] = coef[l * H + tid];
        }
        __syncthreads();

        // ---- Phase A: h = emb @ Wi^T, 8-atom tiles -> half2 ----
#pragma unroll
        for (int t = 0; t < 2; t++) {
            int tile = w + 8 * t;
            if (tile <= 12) {
                int a0 = tile * 8 + half * 4;
                float2 c0 = {0.f, 0.f}, c1 = {0.f, 0.f}, c2 = {0.f, 0.f}, c3 = {0.f, 0.f};
#pragma unroll
                for (int mq = 0; mq < 8; mq++) {
                    const float* eb = s_emb + a0 * H + mq * 4;
                    float4 e0 = *(const float4*)(eb);
                    float4 e1 = *(const float4*)(eb + H);
                    float4 e2 = *(const float4*)(eb + 2 * H);
                    float4 e3 = *(const float4*)(eb + 3 * H);
                    float4 qx = s_Wi4[(mq * 2 + 0) * 16 + lh];
                    float4 qy = s_Wi4[(mq * 2 + 1) * 16 + lh];
#define ACC4(C, E) \
                    C.x = fmaf(E.x, qx.x, fmaf(E.y, qx.y, fmaf(E.z, qx.z, fmaf(E.w, qx.w, C.x)))); \
                    C.y = fmaf(E.x, qy.x, fmaf(E.y, qy.y, fmaf(E.z, qy.z, fmaf(E.w, qy.w, C.y))));
                    ACC4(c0, e0) ACC4(c1, e1) ACC4(c2, e2) ACC4(c3, e3)
#undef ACC4
                }
                if (a0 + 0 < NATOMS) s_hh[(a0 + 0) * HP + lh] = pack_h2(c0.x, c0.y);
                if (a0 + 1 < NATOMS) s_hh[(a0 + 1) * HP + lh] = pack_h2(c1.x, c1.y);
                if (a0 + 2 < NATOMS) s_hh[(a0 + 2) * HP + lh] = pack_h2(c2.x, c2.y);
                if (a0 + 3 < NATOMS) s_hh[(a0 + 3) * HP + lh] = pack_h2(c3.x, c3.y);
            }
        }
        __syncthreads();

        // ---- Phase B1: edge loop -> conv (2 nodes per warp) ----
        const uint2* __restrict__ th = g_tblh + (size_t)l * TBL * HP;
        const float2 cf = *(const float2*)&s_coef[2 * lh];

        for (int i = 0; i < 7; i++) {
            int a  = i * 16 + 2 * w + half;
            int ae = (a < NATOMS) ? a : 0;
            const uint4* ep = (const uint4*)(g_edges + (size_t)(base + ae) * DEG);

            float nx = 0.f, ny = 0.f, denom = 0.f;
#pragma unroll
            for (int grp = 0; grp < 5; grp++) {
                uint4 pq = __ldg(ep + grp);

                float m0x, m0y, m1x, m1y, m2x, m2y, m3x, m3y;
                float q0, q1, q2, q3;
#define EDGE_MSG(P, MX, MY, Q)                                              \
                {                                                           \
                    unsigned p = (P);                                       \
                    float2 hd = unpack_h2(s_hh[(p & 127u) * HP + lh]);      \
                    uint2 tb = __ldg(&th[(((p >> 7) & 4095u) << 4) + lh]);  \
                    float2 vv = unpack_h2(tb.x);                            \
                    float2 ss = unpack_h2(tb.y);                            \
                    float fr = (float)(p >> 19) * (1.0f / 8192.0f);         \
                    MX = hd.x * fmaf(fr, ss.x, vv.x);                       \
                    MY = hd.y * fmaf(fr, ss.y, vv.y);                       \
                    Q  = fmaf(MX, cf.x, MY * cf.y);                         \
                }
                EDGE_MSG(pq.x, m0x, m0y, q0)
                EDGE_MSG(pq.y, m1x, m1y, q1)
                EDGE_MSG(pq.z, m2x, m2y, q2)
                EDGE_MSG(pq.w, m3x, m3y, q3)
#undef EDGE_MSG

                // select-merge butterfly: 4 dots over 16 lanes in 5 shfl
                bool b8 = (lane & 8) != 0;
                float z0  = b8 ? q1 : q0;
                float z0x = b8 ? q0 : q1;
                float m01 = z0 + __shfl_xor_sync(FULL, z0x, 8);
                float z1  = b8 ? q3 : q2;
                float z1x = b8 ? q2 : q3;
                float m23 = z1 + __shfl_xor_sync(FULL, z1x, 8);
                bool b4 = (lane & 4) != 0;
                float z2  = b4 ? m23 : m01;
                float z2x = b4 ? m01 : m23;
                float s = z2 + __shfl_xor_sync(FULL, z2x, 4);
                s += __shfl_xor_sync(FULL, s, 2);
                s += __shfl_xor_sync(FULL, s, 1);
                float av = __expf(s);
                float a0v = __shfl_sync(FULL, av, hb + 0);
                float a1v = __shfl_sync(FULL, av, hb + 8);
                float a2v = __shfl_sync(FULL, av, hb + 4);
                float a3v = __shfl_sync(FULL, av, hb + 12);

                nx = fmaf(m0x, a0v, nx); ny = fmaf(m0y, a0v, ny);
                nx = fmaf(m1x, a1v, nx); ny = fmaf(m1y, a1v, ny);
                nx = fmaf(m2x, a2v, nx); ny = fmaf(m2y, a2v, ny);
                nx = fmaf(m3x, a3v, nx); ny = fmaf(m3y, a3v, ny);
                denom += (a0v + a1v) + (a2v + a3v);
            }

            float cx, cy;
            if (denom > 0.f) {
                float inv = 1.0f / denom;
                cx = nx * inv; cy = ny * inv;
            } else { cx = nx; cy = ny; }

            if (a < NATOMS)
                s_ch[a * HP + lh] = pack_h2(cx, cy);
        }
        __syncthreads();

        // ---- Phase B2: MLP + residual, 8-atom tiles ----
#pragma unroll
        for (int t = 0; t < 2; t++) {
            int tile = w + 8 * t;
            if (tile <= 12) {
                int a0 = tile * 8 + half * 4;
                const float2 b1v = *(const float2*)&s_bo1[2 * lh];
                const float2 b2v = *(const float2*)&s_bo2[2 * lh];

                // matvec1: o1 = tanh(conv @ Wo1^T + b1)
                float2 c0 = b1v, c1 = b1v, c2 = b1v, c3 = b1v;
#pragma unroll
                for (int mq = 0; mq < 8; mq++) {
                    const unsigned* eb = s_ch + a0 * HP + mq * 2;
                    float4 e0 = ld_h4(eb);
                    float4 e1 = ld_h4(eb + HP);
                    float4 e2 = ld_h4(eb + 2 * HP);
                    float4 e3 = ld_h4(eb + 3 * HP);
                    float4 qx = s_Wo14[(mq * 2 + 0) * 16 + lh];
                    float4 qy = s_Wo14[(mq * 2 + 1) * 16 + lh];
#define ACC4(C, E) \
                    C.x = fmaf(E.x, qx.x, fmaf(E.y, qx.y, fmaf(E.z, qx.z, fmaf(E.w, qx.w, C.x)))); \
                    C.y = fmaf(E.x, qy.x, fmaf(E.y, qy.y, fmaf(E.z, qy.z, fmaf(E.w, qy.w, C.y))));
                    ACC4(c0, e0) ACC4(c1, e1) ACC4(c2, e2) ACC4(c3, e3)
#undef ACC4
                }
                c0.x = tanh_fast(c0.x); c0.y = tanh_fast(c0.y);
                c1.x = tanh_fast(c1.x); c1.y = tanh_fast(c1.y);
                c2.x = tanh_fast(c2.x); c2.y = tanh_fast(c2.y);
                c3.x = tanh_fast(c3.x); c3.y = tanh_fast(c3.y);

                __syncwarp();
                s_ch[(a0 + 0) * HP + lh] = pack_h2(c0.x, c0.y);
                s_ch[(a0 + 1) * HP + lh] = pack_h2(c1.x, c1.y);
                s_ch[(a0 + 2) * HP + lh] = pack_h2(c2.x, c2.y);
                s_ch[(a0 + 3) * HP + lh] = pack_h2(c3.x, c3.y);
                __syncwarp();

                // matvec2: o2 = o1 @ Wo2^T + b2
                float2 d0 = b2v, d1 = b2v, d2 = b2v, d3 = b2v;
#pragma unroll
                for (int mq = 0; mq < 8; mq++) {
                    const unsigned* eb = s_ch + a0 * HP + mq * 2;
                    float4 e0 = ld_h4(eb);
                    float4 e1 = ld_h4(eb + HP);
                    float4 e2 = ld_h4(eb + 2 * HP);
                    float4 e3 = ld_h4(eb + 3 * HP);
                    float4 qx = s_Wo24[(mq * 2 + 0) * 16 + lh];
                    float4 qy = s_Wo24[(mq * 2 + 1) * 16 + lh];
#define ACC4(C, E) \
                    C.x = fmaf(E.x, qx.x, fmaf(E.y, qx.y, fmaf(E.z, qx.z, fmaf(E.w, qx.w, C.x)))); \
                    C.y = fmaf(E.x, qy.x, fmaf(E.y, qy.y, fmaf(E.z, qy.z, fmaf(E.w, qy.w, C.y))));
                    ACC4(d0, e0) ACC4(d1, e1) ACC4(d2, e2) ACC4(d3, e3)
#undef ACC4
                }

                // residual / pool
#pragma unroll
                for (int r = 0; r < 4; r++) {
                    int a = a0 + r;
                    if (a < NATOMS) {
                        float2 dd = (r == 0) ? d0 : (r == 1) ? d1 : (r == 2) ? d2 : d3;
                        float2 old = *(const float2*)&s_emb[a * H + 2 * lh];
                        float nex = old.x + dd.x;
                        float ney = old.y + dd.y;
                        if (l < NCONV - 1) {
                            *(float2*)&s_emb[a * H + 2 * lh] = make_float2(nex, ney);
                        } else {
                            pool.x += fmaxf(nex, 0.f);
                            pool.y += fmaxf(ney, 0.f);
                        }
                    }
                }
            }
        }
        __syncthreads();
    }

    // ---- fused pool + final linear ----
    pool.x += __shfl_xor_sync(FULL, pool.x, 16);
    pool.y += __shfl_xor_sync(FULL, pool.y, 16);
    if (lane < 16) {
        s_warp[w * H + 2 * lane]     = pool.x;
        s_warp[w * H + 2 * lane + 1] = pool.y;
    }
    __syncthreads();
    if (w == 0) {
        float p = 0.f;
#pragma unroll
        for (int i = 0; i < 8; i++) p += s_warp[i * H + lane];
        s_pooled[lane] = p * (1.0f / (float)NATOMS);
        __syncwarp();
        if (lane < GDIM) {
            float o = __ldg(&bg[lane]);
#pragma unroll
            for (int k = 0; k < H; k++)
                o = fmaf(s_pooled[k], __ldg(&Wg[lane * H + k]), o);
            out[g * GDIM + lane] = o;
        }
    }
}

// ============================================================
extern "C" void kernel_launch(void* const* d_in, const int* in_sizes, int n_in,
                              void* d_out, int out_size) {
    const float* data      = (const float*)d_in[0];
    const float* emb_table = (const float*)d_in[1];
    const float* W_init    = (const float*)d_in[2];
    const float* Wf1       = (const float*)d_in[3];
    const float* bf1       = (const float*)d_in[4];
    const float* Wf2       = (const float*)d_in[5];
    const float* bf2       = (const float*)d_in[6];
    const float* coef      = (const float*)d_in[7];
    const float* Wo1       = (const float*)d_in[8];
    const float* bo1       = (const float*)d_in[9];
    const float* Wo2       = (const float*)d_in[10];
    const float* bo2       = (const float*)d_in[11];
    const float* Wg        = (const float*)d_in[12];
    const float* bg        = (const float*)d_in[13];
    float* out = (float*)d_out;

    static int smem_set = 0;
    if (!smem_set) {
        cudaFuncSetAttribute(fused_kernel,
                             cudaFuncAttributeMaxDynamicSharedMemorySize,
                             SMEM_BYTES);
        smem_set = 1;
    }

    build_raw_kernel<<<dim3((TBL + 1 + 7) / 8, NCONV), 256>>>(Wf1, bf1, Wf2, bf2);
    pack_edges_kernel<<<(NN * DEG + 255) / 256, 256>>>(data);
    pack_table_kernel<<<(NCONV * TBL * HP + 255) / 256, 256>>>();
    fused_kernel<<<NGRAPH, 256, SMEM_BYTES>>>(emb_table, W_init, coef,
                                              Wo1, bo1, Wo2, bo2, Wg, bg, out);
}

// round 16
// speedup vs baseline: 1.2519x; 1.2519x over previous
#include <cuda_runtime.h>
#include <cuda_fp16.h>
#include <math.h>

#define NN      100000
#define NATOMS  100
#define NGRAPH  1000
#define DEG     20
#define H       32
#define EDIM    51
#define NCONV   3
#define GDIM    16
#define TBL     2048        // he(d) table intervals
#define PADA    104         // padded atom rows (tile 12 covers 96..103)
#define HP      (H / 2)     // 16 half2 per row

// dynamic smem layout (float4 arrays first for alignment)
#define SM_W4      (3 * 256)
#define SM_FLOATS  (PADA * H + 3 * H + 8 * H + H)
#define SM_UINTS   (2 * PADA * HP)
#define SMEM_BYTES (SM_W4 * 16 + SM_FLOATS * 4 + SM_UINTS * 4)

// ---- device scratch ----
__device__ float    g_raw[NCONV * (TBL + 1) * H];   // he at grid points (fp32)
__device__ uint2    g_tblh[NCONV * TBL * HP];       // per lane-pair: {half2 vals, half2 slopes}
__device__ unsigned g_edges[NN * DEG];              // packed (dst_local|i0|fr13)

__device__ __forceinline__ float tanh_fast(float x) {
    float e = __expf(-2.0f * fabsf(x));
    float t = (1.0f - e) / (1.0f + e);
    return copysignf(t, x);
}

__device__ __forceinline__ unsigned pack_h2(float x, float y) {
    __half2 h = __floats2half2_rn(x, y);
    return *(unsigned*)&h;
}
__device__ __forceinline__ float2 unpack_h2(unsigned u) {
    return __half22float2(*(__half2*)&u);
}
// load 4 consecutive half features as float4
__device__ __forceinline__ float4 ld_h4(const unsigned* p) {
    uint2 u = *(const uint2*)p;
    float2 a = unpack_h2(u.x);
    float2 b = unpack_h2(u.y);
    return make_float4(a.x, a.y, b.x, b.y);
}

// ============================================================
// Table build: he_l(d) at TBL+1 grid points.
// ============================================================
__global__ void build_raw_kernel(const float* __restrict__ Wf1,
                                 const float* __restrict__ bf1,
                                 const float* __restrict__ Wf2,
                                 const float* __restrict__ bf2) {
    const int l = blockIdx.y;
    __shared__ float s_Wf1[H * EDIM];
    __shared__ float s_Wf2T[H * H];
    __shared__ float s_bf1[H], s_bf2[H];
    __shared__ float s_ee[8][EDIM];
    __shared__ float s_f1[8][H];

    int tid = threadIdx.x;
    for (int i = tid; i < H * EDIM; i += blockDim.x)
        s_Wf1[i] = Wf1[l * H * EDIM + i];
    for (int i = tid; i < H * H; i += blockDim.x) {
        int k = i / H, m = i % H;
        s_Wf2T[m * H + k] = Wf2[l * H * H + i];
    }
    if (tid < H) { s_bf1[tid] = bf1[l * H + tid]; s_bf2[tid] = bf2[l * H + tid]; }
    __syncthreads();

    int w = tid >> 5, lane = tid & 31;
    int t = blockIdx.x * 8 + w;
    if (t > TBL) return;
    float d = (float)t * (10.0f / (float)TBL);

    for (int j = lane; j < EDIM; j += 32) {
        float dc = d - 0.2f * (float)j;
        s_ee[w][j] = __expf(-25.0f * dc * dc);
    }
    __syncwarp();

    float acc = s_bf1[lane];
    for (int j = 0; j < EDIM; j++)
        acc = fmaf(s_ee[w][j], s_Wf1[lane * EDIM + j], acc);
    s_f1[w][lane] = tanh_fast(acc);
    __syncwarp();

    float he = s_bf2[lane];
#pragma unroll
    for (int m = 0; m < H; m++)
        he = fmaf(s_f1[w][m], s_Wf2T[m * H + lane], he);
    g_raw[(l * (TBL + 1) + t) * H + lane] = he;
}

// pack half2 (vals, slopes) per feature pair
__global__ void pack_table_kernel() {
    int idx = blockIdx.x * blockDim.x + threadIdx.x;   // over NCONV*TBL*16
    if (idx >= NCONV * TBL * HP) return;
    int l  = idx / (TBL * HP);
    int r  = idx - l * (TBL * HP);
    int i  = r >> 4;            // interval
    int fp = r & 15;            // feature pair
    const float* r0 = g_raw + (l * (TBL + 1) + i) * H + 2 * fp;
    const float* r1 = r0 + H;
    float v0 = r0[0], v1 = r0[1];
    float s0 = r1[0] - v0, s1 = r1[1] - v1;
    uint2 e;
    e.x = pack_h2(v0, v1);
    e.y = pack_h2(s0, s1);
    g_tblh[idx] = e;
}

// ============================================================
// Edge pre-pack: bits [0:7) dst_local, [7:19) i0, [19:32) fr*8192
// ============================================================
__global__ void pack_edges_kernel(const float* __restrict__ data) {
    int e = blockIdx.x * blockDim.x + threadIdx.x;
    if (e >= NN * DEG) return;
    int src   = e / DEG;
    int base  = (src / NATOMS) * NATOMS;
    int dl    = (int)data[e * 3 + 1] - base;
    float u   = data[e * 3 + 2] * ((float)TBL * 0.1f);
    int i0    = min((int)u, TBL - 1);
    int fri   = min((int)((u - (float)i0) * 8192.0f), 8191);
    g_edges[e] = (unsigned)dl | ((unsigned)i0 << 7) | ((unsigned)fri << 19);
}

// ============================================================
// Fused 3-layer kernel: block per graph (dynamic smem).
// s_h / s_conv staged as half2 (halves B1 gather wavefronts).
// 64-reg budget (4 blocks/SM) -- no spills.
// ============================================================
__global__ void __launch_bounds__(256, 4)
fused_kernel(const float* __restrict__ emb_table,
             const float* __restrict__ W_init,
             const float* __restrict__ coef,
             const float* __restrict__ Wo1, const float* __restrict__ bo1,
             const float* __restrict__ Wo2, const float* __restrict__ bo2,
             const float* __restrict__ Wg,  const float* __restrict__ bg,
             float* __restrict__ out) {
    extern __shared__ float4 smem4[];
    float4* s_Wi4  = smem4;            // 256 float4
    float4* s_Wo14 = smem4 + 256;
    float4* s_Wo24 = smem4 + 512;
    float*  fbase  = (float*)(smem4 + SM_W4);
    float*  s_emb  = fbase;                       // PADA*H
    float*  s_bo1  = s_emb  + PADA * H;           // H
    float*  s_bo2  = s_bo1  + H;                  // H
    float*  s_coef = s_bo2  + H;                  // H
    float*  s_warp = s_coef + H;                  // 8*H
    float*  s_pooled = s_warp + 8 * H;            // H
    unsigned* s_hh = (unsigned*)(s_pooled + H);   // PADA*HP (half2 h)
    unsigned* s_ch = s_hh + PADA * HP;            // PADA*HP (half2 conv/o1)

    const int tid  = threadIdx.x;
    const int w    = tid >> 5;
    const int lane = tid & 31;
    const int lh   = lane & 15;      // feature pair index
    const int hb   = lane & 16;      // half base
    const int half = hb >> 4;
    const int g    = blockIdx.x;
    const int base = g * NATOMS;
    const unsigned FULL = 0xffffffffu;

    // init embeddings; zero pad rows of all staging arrays
    for (int i = tid; i < NATOMS * H; i += 256) s_emb[i] = emb_table[i];
    for (int i = NATOMS * H + tid; i < PADA * H; i += 256) s_emb[i] = 0.f;
    for (int i = NATOMS * HP + tid; i < PADA * HP; i += 256) {
        s_hh[i] = 0u; s_ch[i] = 0u;
    }

    float2 pool = make_float2(0.f, 0.f);

    // weight-pack indices (one float4 per thread per matrix)
    const int pmq = tid >> 5;            // m-quad 0..7
    const int pj  = (tid >> 4) & 1;      // column parity
    const int pf  = tid & 15;            // feature pair
    const int pdst = (pmq * 2 + pj) * 16 + pf;
    const int psrc = (2 * pf + pj) * H + 4 * pmq;

    for (int l = 0; l < NCONV; l++) {
        // ---- pack weights as column quads ----
        s_Wi4 [pdst] = *(const float4*)&W_init[l * H * H + psrc];
        s_Wo14[pdst] = *(const float4*)&Wo1   [l * H * H + psrc];
        s_Wo24[pdst] = *(const float4*)&Wo2   [l * H * H + psrc];
        if (tid < H) {
            s_bo1[tid]  = bo1[l * H + tid];
            s_bo2[tid]  = bo2[l * H + tid];
            s_coef[tid] = coef[l * H + tid];
        }
        __syncthreads();

        // ---- Phase A: h = emb @ Wi^T, 8-atom tiles -> half2 ----
#pragma unroll
        for (int t = 0; t < 2; t++) {
            int tile = w + 8 * t;
            if (tile <= 12) {
                int a0 = tile * 8 + half * 4;
                float2 c0 = {0.f, 0.f}, c1 = {0.f, 0.f}, c2 = {0.f, 0.f}, c3 = {0.f, 0.f};
#pragma unroll
                for (int mq = 0; mq < 8; mq++) {
                    const float* eb = s_emb + a0 * H + mq * 4;
                    float4 e0 = *(const float4*)(eb);
                    float4 e1 = *(const float4*)(eb + H);
                    float4 e2 = *(const float4*)(eb + 2 * H);
                    float4 e3 = *(const float4*)(eb + 3 * H);
                    float4 qx = s_Wi4[(mq * 2 + 0) * 16 + lh];
                    float4 qy = s_Wi4[(mq * 2 + 1) * 16 + lh];
#define ACC4(C, E) \
                    C.x = fmaf(E.x, qx.x, fmaf(E.y, qx.y, fmaf(E.z, qx.z, fmaf(E.w, qx.w, C.x)))); \
                    C.y = fmaf(E.x, qy.x, fmaf(E.y, qy.y, fmaf(E.z, qy.z, fmaf(E.w, qy.w, C.y))));
                    ACC4(c0, e0) ACC4(c1, e1) ACC4(c2, e2) ACC4(c3, e3)
#undef ACC4
                }
                if (a0 + 0 < NATOMS) s_hh[(a0 + 0) * HP + lh] = pack_h2(c0.x, c0.y);
                if (a0 + 1 < NATOMS) s_hh[(a0 + 1) * HP + lh] = pack_h2(c1.x, c1.y);
                if (a0 + 2 < NATOMS) s_hh[(a0 + 2) * HP + lh] = pack_h2(c2.x, c2.y);
                if (a0 + 3 < NATOMS) s_hh[(a0 + 3) * HP + lh] = pack_h2(c3.x, c3.y);
            }
        }
        __syncthreads();

        // ---- Phase B1: edge loop -> conv (2 nodes per warp) ----
        const uint2* __restrict__ th = g_tblh + (size_t)l * TBL * HP;
        const float2 cf = *(const float2*)&s_coef[2 * lh];

        for (int i = 0; i < 7; i++) {
            int a  = i * 16 + 2 * w + half;
            int ae = (a < NATOMS) ? a : 0;
            const uint4* ep = (const uint4*)(g_edges + (size_t)(base + ae) * DEG);

            float nx = 0.f, ny = 0.f, denom = 0.f;
#pragma unroll
            for (int grp = 0; grp < 5; grp++) {
                uint4 pq = __ldg(ep + grp);

                float m0x, m0y, m1x, m1y, m2x, m2y, m3x, m3y;
                float q0, q1, q2, q3;
#define EDGE_MSG(P, MX, MY, Q)                                              \
                {                                                           \
                    unsigned p = (P);                                       \
                    float2 hd = unpack_h2(s_hh[(p & 127u) * HP + lh]);      \
                    uint2 tb = __ldg(&th[(((p >> 7) & 4095u) << 4) + lh]);  \
                    float2 vv = unpack_h2(tb.x);                            \
                    float2 ss = unpack_h2(tb.y);                            \
                    float fr = (float)(p >> 19) * (1.0f / 8192.0f);         \
                    MX = hd.x * fmaf(fr, ss.x, vv.x);                       \
                    MY = hd.y * fmaf(fr, ss.y, vv.y);                       \
                    Q  = fmaf(MX, cf.x, MY * cf.y);                         \
                }
                EDGE_MSG(pq.x, m0x, m0y, q0)
                EDGE_MSG(pq.y, m1x, m1y, q1)
                EDGE_MSG(pq.z, m2x, m2y, q2)
                EDGE_MSG(pq.w, m3x, m3y, q3)
#undef EDGE_MSG

                // select-merge butterfly: 4 dots over 16 lanes in 5 shfl
                bool b8 = (lane & 8) != 0;
                float z0  = b8 ? q1 : q0;
                float z0x = b8 ? q0 : q1;
                float m01 = z0 + __shfl_xor_sync(FULL, z0x, 8);
                float z1  = b8 ? q3 : q2;
                float z1x = b8 ? q2 : q3;
                float m23 = z1 + __shfl_xor_sync(FULL, z1x, 8);
                bool b4 = (lane & 4) != 0;
                float z2  = b4 ? m23 : m01;
                float z2x = b4 ? m01 : m23;
                float s = z2 + __shfl_xor_sync(FULL, z2x, 4);
                s += __shfl_xor_sync(FULL, s, 2);
                s += __shfl_xor_sync(FULL, s, 1);
                float av = __expf(s);
                float a0v = __shfl_sync(FULL, av, hb + 0);
                float a1v = __shfl_sync(FULL, av, hb + 8);
                float a2v = __shfl_sync(FULL, av, hb + 4);
                float a3v = __shfl_sync(FULL, av, hb + 12);

                nx = fmaf(m0x, a0v, nx); ny = fmaf(m0y, a0v, ny);
                nx = fmaf(m1x, a1v, nx); ny = fmaf(m1y, a1v, ny);
                nx = fmaf(m2x, a2v, nx); ny = fmaf(m2y, a2v, ny);
                nx = fmaf(m3x, a3v, nx); ny = fmaf(m3y, a3v, ny);
                denom += (a0v + a1v) + (a2v + a3v);
            }

            float cx, cy;
            if (denom > 0.f) {
                float inv = 1.0f / denom;
                cx = nx * inv; cy = ny * inv;
            } else { cx = nx; cy = ny; }

            if (a < NATOMS)
                s_ch[a * HP + lh] = pack_h2(cx, cy);
        }
        __syncthreads();

        // ---- Phase B2: MLP + residual, 8-atom tiles ----
#pragma unroll
        for (int t = 0; t < 2; t++) {
            int tile = w + 8 * t;
            if (tile <= 12) {
                int a0 = tile * 8 + half * 4;
                const float2 b1v = *(const float2*)&s_bo1[2 * lh];
                const float2 b2v = *(const float2*)&s_bo2[2 * lh];

                // matvec1: o1 = tanh(conv @ Wo1^T + b1)
                float2 c0 = b1v, c1 = b1v, c2 = b1v, c3 = b1v;
#pragma unroll
                for (int mq = 0; mq < 8; mq++) {
                    const unsigned* eb = s_ch + a0 * HP + mq * 2;
                    float4 e0 = ld_h4(eb);
                    float4 e1 = ld_h4(eb + HP);
                    float4 e2 = ld_h4(eb + 2 * HP);
                    float4 e3 = ld_h4(eb + 3 * HP);
                    float4 qx = s_Wo14[(mq * 2 + 0) * 16 + lh];
                    float4 qy = s_Wo14[(mq * 2 + 1) * 16 + lh];
#define ACC4(C, E) \
                    C.x = fmaf(E.x, qx.x, fmaf(E.y, qx.y, fmaf(E.z, qx.z, fmaf(E.w, qx.w, C.x)))); \
                    C.y = fmaf(E.x, qy.x, fmaf(E.y, qy.y, fmaf(E.z, qy.z, fmaf(E.w, qy.w, C.y))));
                    ACC4(c0, e0) ACC4(c1, e1) ACC4(c2, e2) ACC4(c3, e3)
#undef ACC4
                }
                c0.x = tanh_fast(c0.x); c0.y = tanh_fast(c0.y);
                c1.x = tanh_fast(c1.x); c1.y = tanh_fast(c1.y);
                c2.x = tanh_fast(c2.x); c2.y = tanh_fast(c2.y);
                c3.x = tanh_fast(c3.x); c3.y = tanh_fast(c3.y);

                __syncwarp();
                s_ch[(a0 + 0) * HP + lh] = pack_h2(c0.x, c0.y);
                s_ch[(a0 + 1) * HP + lh] = pack_h2(c1.x, c1.y);
                s_ch[(a0 + 2) * HP + lh] = pack_h2(c2.x, c2.y);
                s_ch[(a0 + 3) * HP + lh] = pack_h2(c3.x, c3.y);
                __syncwarp();

                // matvec2: o2 = o1 @ Wo2^T + b2
                float2 d0 = b2v, d1 = b2v, d2 = b2v, d3 = b2v;
#pragma unroll
                for (int mq = 0; mq < 8; mq++) {
                    const unsigned* eb = s_ch + a0 * HP + mq * 2;
                    float4 e0 = ld_h4(eb);
                    float4 e1 = ld_h4(eb + HP);
                    float4 e2 = ld_h4(eb + 2 * HP);
                    float4 e3 = ld_h4(eb + 3 * HP);
                    float4 qx = s_Wo24[(mq * 2 + 0) * 16 + lh];
                    float4 qy = s_Wo24[(mq * 2 + 1) * 16 + lh];
#define ACC4(C, E) \
                    C.x = fmaf(E.x, qx.x, fmaf(E.y, qx.y, fmaf(E.z, qx.z, fmaf(E.w, qx.w, C.x)))); \
                    C.y = fmaf(E.x, qy.x, fmaf(E.y, qy.y, fmaf(E.z, qy.z, fmaf(E.w, qy.w, C.y))));
                    ACC4(d0, e0) ACC4(d1, e1) ACC4(d2, e2) ACC4(d3, e3)
#undef ACC4
                }

                // residual / pool
#pragma unroll
                for (int r = 0; r < 4; r++) {
                    int a = a0 + r;
                    if (a < NATOMS) {
                        float2 dd = (r == 0) ? d0 : (r == 1) ? d1 : (r == 2) ? d2 : d3;
                        float2 old = *(const float2*)&s_emb[a * H + 2 * lh];
                        float nex = old.x + dd.x;
                        float ney = old.y + dd.y;
                        if (l < NCONV - 1) {
                            *(float2*)&s_emb[a * H + 2 * lh] = make_float2(nex, ney);
                        } else {
                            pool.x += fmaxf(nex, 0.f);
                            pool.y += fmaxf(ney, 0.f);
                        }
                    }
                }
            }
        }
        __syncthreads();
    }

    // ---- fused pool + final linear ----
    pool.x += __shfl_xor_sync(FULL, pool.x, 16);
    pool.y += __shfl_xor_sync(FULL, pool.y, 16);
    if (lane < 16) {
        s_warp[w * H + 2 * lane]     = pool.x;
        s_warp[w * H + 2 * lane + 1] = pool.y;
    }
    __syncthreads();
    if (w == 0) {
        float p = 0.f;
#pragma unroll
        for (int i = 0; i < 8; i++) p += s_warp[i * H + lane];
        s_pooled[lane] = p * (1.0f / (float)NATOMS);
        __syncwarp();
        if (lane < GDIM) {
            float o = __ldg(&bg[lane]);
#pragma unroll
            for (int k = 0; k < H; k++)
                o = fmaf(s_pooled[k], __ldg(&Wg[lane * H + k]), o);
            out[g * GDIM + lane] = o;
        }
    }
}

// ============================================================
extern "C" void kernel_launch(void* const* d_in, const int* in_sizes, int n_in,
                              void* d_out, int out_size) {
    const float* data      = (const float*)d_in[0];
    const float* emb_table = (const float*)d_in[1];
    const float* W_init    = (const float*)d_in[2];
    const float* Wf1       = (const float*)d_in[3];
    const float* bf1       = (const float*)d_in[4];
    const float* Wf2       = (const float*)d_in[5];
    const float* bf2       = (const float*)d_in[6];
    const float* coef      = (const float*)d_in[7];
    const float* Wo1       = (const float*)d_in[8];
    const float* bo1       = (const float*)d_in[9];
    const float* Wo2       = (const float*)d_in[10];
    const float* bo2       = (const float*)d_in[11];
    const float* Wg        = (const float*)d_in[12];
    const float* bg        = (const float*)d_in[13];
    float* out = (float*)d_out;

    static int smem_set = 0;
    if (!smem_set) {
        cudaFuncSetAttribute(fused_kernel,
                             cudaFuncAttributeMaxDynamicSharedMemorySize,
                             SMEM_BYTES);
        smem_set = 1;
    }

    build_raw_kernel<<<dim3((TBL + 1 + 7) / 8, NCONV), 256>>>(Wf1, bf1, Wf2, bf2);
    pack_edges_kernel<<<(NN * DEG + 255) / 256, 256>>>(data);
    pack_table_kernel<<<(NCONV * TBL * HP + 255) / 256, 256>>>();
    fused_kernel<<<NGRAPH, 256, SMEM_BYTES>>>(emb_table, W_init, coef,
                                              Wo1, bo1, Wo2, bo2, Wg, bg, out);
}

// round 17
// speedup vs baseline: 1.2942x; 1.0337x over previous
#include <cuda_runtime.h>
#include <cuda_fp16.h>
#include <math.h>

#define NN      100000
#define NATOMS  100
#define NGRAPH  1000
#define DEG     20
#define H       32
#define EDIM    51
#define NCONV   3
#define GDIM    16
#define TBL     2048        // he(d) table intervals
#define PADA    104         // padded atom rows (tile 12 covers 96..103)
#define HP      (H / 2)

// dynamic smem layout (float4 arrays first for alignment)
#define SM_W4      (3 * 256)
#define SM_FLOATS  (3 * PADA * H + 3 * H + 8 * H + H)
#define SMEM_BYTES (SM_W4 * 16 + SM_FLOATS * 4)

// ---- device scratch ----
__device__ float    g_raw[NCONV * (TBL + 1) * H];   // he at grid points (fp32)
__device__ uint2    g_tblh[NCONV * TBL * HP];       // per lane-pair: {half2 vals, half2 slopes}
__device__ unsigned g_edges[NN * DEG];              // packed (dst_local|i0|fr13)

__device__ __forceinline__ float tanh_fast(float x) {
    float e = __expf(-2.0f * fabsf(x));
    float t = (1.0f - e) / (1.0f + e);
    return copysignf(t, x);
}
__device__ __forceinline__ float2 unpack_h2(unsigned u) {
    return __half22float2(*(__half2*)&u);
}

// ============================================================
// Table build: he_l(d) at TBL+1 grid points.
// ============================================================
__global__ void build_raw_kernel(const float* __restrict__ Wf1,
                                 const float* __restrict__ bf1,
                                 const float* __restrict__ Wf2,
                                 const float* __restrict__ bf2) {
    const int l = blockIdx.y;
    __shared__ float s_Wf1[H * EDIM];
    __shared__ float s_Wf2T[H * H];
    __shared__ float s_bf1[H], s_bf2[H];
    __shared__ float s_ee[8][EDIM];
    __shared__ float s_f1[8][H];

    int tid = threadIdx.x;
    for (int i = tid; i < H * EDIM; i += blockDim.x)
        s_Wf1[i] = Wf1[l * H * EDIM + i];
    for (int i = tid; i < H * H; i += blockDim.x) {
        int k = i / H, m = i % H;
        s_Wf2T[m * H + k] = Wf2[l * H * H + i];
    }
    if (tid < H) { s_bf1[tid] = bf1[l * H + tid]; s_bf2[tid] = bf2[l * H + tid]; }
    __syncthreads();

    int w = tid >> 5, lane = tid & 31;
    int t = blockIdx.x * 8 + w;
    if (t > TBL) return;
    float d = (float)t * (10.0f / (float)TBL);

    for (int j = lane; j < EDIM; j += 32) {
        float dc = d - 0.2f * (float)j;
        s_ee[w][j] = __expf(-25.0f * dc * dc);
    }
    __syncwarp();

    float acc = s_bf1[lane];
    for (int j = 0; j < EDIM; j++)
        acc = fmaf(s_ee[w][j], s_Wf1[lane * EDIM + j], acc);
    s_f1[w][lane] = tanh_fast(acc);
    __syncwarp();

    float he = s_bf2[lane];
#pragma unroll
    for (int m = 0; m < H; m++)
        he = fmaf(s_f1[w][m], s_Wf2T[m * H + lane], he);
    g_raw[(l * (TBL + 1) + t) * H + lane] = he;
}

// pack half2 (vals, slopes) per feature pair
__global__ void pack_table_kernel() {
    int idx = blockIdx.x * blockDim.x + threadIdx.x;   // over NCONV*TBL*16
    if (idx >= NCONV * TBL * HP) return;
    int l  = idx / (TBL * HP);
    int r  = idx - l * (TBL * HP);
    int i  = r >> 4;            // interval
    int fp = r & 15;            // feature pair
    const float* r0 = g_raw + (l * (TBL + 1) + i) * H + 2 * fp;
    const float* r1 = r0 + H;
    float v0 = r0[0], v1 = r0[1];
    float s0 = r1[0] - v0, s1 = r1[1] - v1;
    __half2 hv = __floats2half2_rn(v0, v1);
    __half2 hs = __floats2half2_rn(s0, s1);
    uint2 e;
    e.x = *(unsigned*)&hv;
    e.y = *(unsigned*)&hs;
    g_tblh[idx] = e;
}

// ============================================================
// Edge pre-pack: bits [0:7) dst_local, [7:19) i0, [19:32) fr*8192
// ============================================================
__global__ void pack_edges_kernel(const float* __restrict__ data) {
    int e = blockIdx.x * blockDim.x + threadIdx.x;
    if (e >= NN * DEG) return;
    int src   = e / DEG;
    int base  = (src / NATOMS) * NATOMS;
    int dl    = (int)data[e * 3 + 1] - base;
    float u   = data[e * 3 + 2] * ((float)TBL * 0.1f);
    int i0    = min((int)u, TBL - 1);
    int fri   = min((int)((u - (float)i0) * 8192.0f), 8191);
    g_edges[e] = (unsigned)dl | ((unsigned)i0 << 7) | ((unsigned)fri << 19);
}

// ============================================================
// Fused 3-layer kernel: block per graph (dynamic smem).
// fp32 staging (R14); edge loop interleaves TWO node iterations
// so their shfl-reduction chains overlap (ILP vs latency).
// ============================================================
__global__ void __launch_bounds__(256, 4)
fused_kernel(const float* __restrict__ emb_table,
             const float* __restrict__ W_init,
             const float* __restrict__ coef,
             const float* __restrict__ Wo1, const float* __restrict__ bo1,
             const float* __restrict__ Wo2, const float* __restrict__ bo2,
             const float* __restrict__ Wg,  const float* __restrict__ bg,
             float* __restrict__ out) {
    extern __shared__ float4 smem4[];
    float4* s_Wi4  = smem4;            // 256 float4
    float4* s_Wo14 = smem4 + 256;
    float4* s_Wo24 = smem4 + 512;
    float*  fbase  = (float*)(smem4 + SM_W4);
    float*  s_emb  = fbase;                       // PADA*H
    float*  s_h    = s_emb  + PADA * H;           // PADA*H
    float*  s_conv = s_h    + PADA * H;           // PADA*H
    float*  s_bo1  = s_conv + PADA * H;           // H
    float*  s_bo2  = s_bo1  + H;                  // H
    float*  s_coef = s_bo2  + H;                  // H
    float*  s_warp = s_coef + H;                  // 8*H
    float*  s_pooled = s_warp + 8 * H;            // H

    const int tid  = threadIdx.x;
    const int w    = tid >> 5;
    const int lane = tid & 31;
    const int lh   = lane & 15;
    const int hb   = lane & 16;
    const int half = hb >> 4;
    const int g    = blockIdx.x;
    const int base = g * NATOMS;
    const unsigned FULL = 0xffffffffu;

    for (int i = tid; i < NATOMS * H; i += 256) s_emb[i] = emb_table[i];
    for (int i = NATOMS * H + tid; i < PADA * H; i += 256) {
        s_emb[i] = 0.f; s_h[i] = 0.f; s_conv[i] = 0.f;
    }

    float2 pool = make_float2(0.f, 0.f);

    const int pmq = tid >> 5;
    const int pj  = (tid >> 4) & 1;
    const int pf  = tid & 15;
    const int pdst = (pmq * 2 + pj) * 16 + pf;
    const int psrc = (2 * pf + pj) * H + 4 * pmq;

    for (int l = 0; l < NCONV; l++) {
        s_Wi4 [pdst] = *(const float4*)&W_init[l * H * H + psrc];
        s_Wo14[pdst] = *(const float4*)&Wo1   [l * H * H + psrc];
        s_Wo24[pdst] = *(const float4*)&Wo2   [l * H * H + psrc];
        if (tid < H) {
            s_bo1[tid]  = bo1[l * H + tid];
            s_bo2[tid]  = bo2[l * H + tid];
            s_coef[tid] = coef[l * H + tid];
        }
        __syncthreads();

        // ---- Phase A: h = emb @ Wi^T, 8-atom tiles ----
#pragma unroll
        for (int t = 0; t < 2; t++) {
            int tile = w + 8 * t;
            if (tile <= 12) {
                int a0 = tile * 8 + half * 4;
                float2 c0 = {0.f, 0.f}, c1 = {0.f, 0.f}, c2 = {0.f, 0.f}, c3 = {0.f, 0.f};
#pragma unroll
                for (int mq = 0; mq < 8; mq++) {
                    const float* eb = s_emb + a0 * H + mq * 4;
                    float4 e0 = *(const float4*)(eb);
                    float4 e1 = *(const float4*)(eb + H);
                    float4 e2 = *(const float4*)(eb + 2 * H);
                    float4 e3 = *(const float4*)(eb + 3 * H);
                    float4 qx = s_Wi4[(mq * 2 + 0) * 16 + lh];
                    float4 qy = s_Wi4[(mq * 2 + 1) * 16 + lh];
#define ACC4(C, E) \
                    C.x = fmaf(E.x, qx.x, fmaf(E.y, qx.y, fmaf(E.z, qx.z, fmaf(E.w, qx.w, C.x)))); \
                    C.y = fmaf(E.x, qy.x, fmaf(E.y, qy.y, fmaf(E.z, qy.z, fmaf(E.w, qy.w, C.y))));
                    ACC4(c0, e0) ACC4(c1, e1) ACC4(c2, e2) ACC4(c3, e3)
#undef ACC4
                }
                if (a0 + 0 < NATOMS) *(float2*)&s_h[(a0 + 0) * H + 2 * lh] = c0;
                if (a0 + 1 < NATOMS) *(float2*)&s_h[(a0 + 1) * H + 2 * lh] = c1;
                if (a0 + 2 < NATOMS) *(float2*)&s_h[(a0 + 2) * H + 2 * lh] = c2;
                if (a0 + 3 < NATOMS) *(float2*)&s_h[(a0 + 3) * H + 2 * lh] = c3;
            }
        }
        __syncthreads();

        // ---- Phase B1: edge loop, 2 node-iterations interleaved ----
        const uint2* __restrict__ th = g_tblh + (size_t)l * TBL * HP;
        const float2 cf = *(const float2*)&s_coef[2 * lh];

#define EDGE_MSG(P, MX, MY, Q)                                              \
        {                                                                   \
            unsigned p = (P);                                               \
            float2 hd = *(const float2*)&s_h[(p & 127u) * H + 2 * lh];      \
            uint2 tb = __ldg(&th[(((p >> 7) & 4095u) << 4) + lh]);          \
            float2 vv = unpack_h2(tb.x);                                    \
            float2 ss = unpack_h2(tb.y);                                    \
            float fr = (float)(p >> 19) * (1.0f / 8192.0f);                 \
            MX = hd.x * fmaf(fr, ss.x, vv.x);                               \
            MY = hd.y * fmaf(fr, ss.y, vv.y);                               \
            Q  = fmaf(MX, cf.x, MY * cf.y);                                 \
        }
// butterfly: reduce 4 dots (Q0..Q3) over 16-lane halves, produce A0..A3
#define BUTTERFLY(Q0, Q1, Q2, Q3, A0, A1, A2, A3)                           \
        {                                                                   \
            bool b8 = (lane & 8) != 0;                                      \
            float z0  = b8 ? Q1 : Q0;                                       \
            float z0x = b8 ? Q0 : Q1;                                       \
            float m01 = z0 + __shfl_xor_sync(FULL, z0x, 8);                 \
            float z1  = b8 ? Q3 : Q2;                                       \
            float z1x = b8 ? Q2 : Q3;                                       \
            float m23 = z1 + __shfl_xor_sync(FULL, z1x, 8);                 \
            bool b4 = (lane & 4) != 0;                                      \
            float z2  = b4 ? m23 : m01;                                     \
            float z2x = b4 ? m01 : m23;                                     \
            float s = z2 + __shfl_xor_sync(FULL, z2x, 4);                   \
            s += __shfl_xor_sync(FULL, s, 2);                               \
            s += __shfl_xor_sync(FULL, s, 1);                               \
            float av = __expf(s);                                           \
            A0 = __shfl_sync(FULL, av, hb + 0);                             \
            A1 = __shfl_sync(FULL, av, hb + 8);                             \
            A2 = __shfl_sync(FULL, av, hb + 4);                             \
            A3 = __shfl_sync(FULL, av, hb + 12);                            \
        }

        for (int i = 0; i < 6; i += 2) {
            int aA  = i * 16 + 2 * w + half;
            int aB  = aA + 16;
            int aeA = (aA < NATOMS) ? aA : 0;
            int aeB = (aB < NATOMS) ? aB : 0;
            const uint4* epA = (const uint4*)(g_edges + (size_t)(base + aeA) * DEG);
            const uint4* epB = (const uint4*)(g_edges + (size_t)(base + aeB) * DEG);

            float nxA = 0.f, nyA = 0.f, dnA = 0.f;
            float nxB = 0.f, nyB = 0.f, dnB = 0.f;
#pragma unroll
            for (int grp = 0; grp < 5; grp++) {
                uint4 pqA = __ldg(epA + grp);
                uint4 pqB = __ldg(epB + grp);

                float a0x, a0y, a1x, a1y, a2x, a2y, a3x, a3y;
                float b0x, b0y, b1x, b1y, b2x, b2y, b3x, b3y;
                float qa0, qa1, qa2, qa3, qb0, qb1, qb2, qb3;
                EDGE_MSG(pqA.x, a0x, a0y, qa0)
                EDGE_MSG(pqA.y, a1x, a1y, qa1)
                EDGE_MSG(pqA.z, a2x, a2y, qa2)
                EDGE_MSG(pqA.w, a3x, a3y, qa3)
                EDGE_MSG(pqB.x, b0x, b0y, qb0)
                EDGE_MSG(pqB.y, b1x, b1y, qb1)
                EDGE_MSG(pqB.z, b2x, b2y, qb2)
                EDGE_MSG(pqB.w, b3x, b3y, qb3)

                float aa0, aa1, aa2, aa3, ab0, ab1, ab2, ab3;
                BUTTERFLY(qa0, qa1, qa2, qa3, aa0, aa1, aa2, aa3)
                BUTTERFLY(qb0, qb1, qb2, qb3, ab0, ab1, ab2, ab3)

                nxA = fmaf(a0x, aa0, nxA); nyA = fmaf(a0y, aa0, nyA);
                nxA = fmaf(a1x, aa1, nxA); nyA = fmaf(a1y, aa1, nyA);
                nxA = fmaf(a2x, aa2, nxA); nyA = fmaf(a2y, aa2, nyA);
                nxA = fmaf(a3x, aa3, nxA); nyA = fmaf(a3y, aa3, nyA);
                dnA += (aa0 + aa1) + (aa2 + aa3);

                nxB = fmaf(b0x, ab0, nxB); nyB = fmaf(b0y, ab0, nyB);
                nxB = fmaf(b1x, ab1, nxB); nyB = fmaf(b1y, ab1, nyB);
                nxB = fmaf(b2x, ab2, nxB); nyB = fmaf(b2y, ab2, nyB);
                nxB = fmaf(b3x, ab3, nxB); nyB = fmaf(b3y, ab3, nyB);
                dnB += (ab0 + ab1) + (ab2 + ab3);
            }

            float cxA, cyA, cxB, cyB;
            if (dnA > 0.f) { float inv = 1.0f / dnA; cxA = nxA * inv; cyA = nyA * inv; }
            else           { cxA = nxA; cyA = nyA; }
            if (dnB > 0.f) { float inv = 1.0f / dnB; cxB = nxB * inv; cyB = nyB * inv; }
            else           { cxB = nxB; cyB = nyB; }

            if (aA < NATOMS) *(float2*)&s_conv[aA * H + 2 * lh] = make_float2(cxA, cyA);
            if (aB < NATOMS) *(float2*)&s_conv[aB * H + 2 * lh] = make_float2(cxB, cyB);
        }

        // tail: i = 6 (nodes 96..99 + inactive slots)
        {
            int a  = 6 * 16 + 2 * w + half;
            int ae = (a < NATOMS) ? a : 0;
            const uint4* ep = (const uint4*)(g_edges + (size_t)(base + ae) * DEG);
            float nx = 0.f, ny = 0.f, dn = 0.f;
#pragma unroll
            for (int grp = 0; grp < 5; grp++) {
                uint4 pq = __ldg(ep + grp);
                float m0x, m0y, m1x, m1y, m2x, m2y, m3x, m3y;
                float q0, q1, q2, q3;
                EDGE_MSG(pq.x, m0x, m0y, q0)
                EDGE_MSG(pq.y, m1x, m1y, q1)
                EDGE_MSG(pq.z, m2x, m2y, q2)
                EDGE_MSG(pq.w, m3x, m3y, q3)
                float a0v, a1v, a2v, a3v;
                BUTTERFLY(q0, q1, q2, q3, a0v, a1v, a2v, a3v)
                nx = fmaf(m0x, a0v, nx); ny = fmaf(m0y, a0v, ny);
                nx = fmaf(m1x, a1v, nx); ny = fmaf(m1y, a1v, ny);
                nx = fmaf(m2x, a2v, nx); ny = fmaf(m2y, a2v, ny);
                nx = fmaf(m3x, a3v, nx); ny = fmaf(m3y, a3v, ny);
                dn += (a0v + a1v) + (a2v + a3v);
            }
            float cx, cy;
            if (dn > 0.f) { float inv = 1.0f / dn; cx = nx * inv; cy = ny * inv; }
            else          { cx = nx; cy = ny; }
            if (a < NATOMS) *(float2*)&s_conv[a * H + 2 * lh] = make_float2(cx, cy);
        }
#undef EDGE_MSG
#undef BUTTERFLY
        __syncthreads();

        // ---- Phase B2: MLP + residual, 8-atom tiles ----
#pragma unroll
        for (int t = 0; t < 2; t++) {
            int tile = w + 8 * t;
            if (tile <= 12) {
                int a0 = tile * 8 + half * 4;
                const float2 b1v = *(const float2*)&s_bo1[2 * lh];
                const float2 b2v = *(const float2*)&s_bo2[2 * lh];

                float2 c0 = b1v, c1 = b1v, c2 = b1v, c3 = b1v;
#pragma unroll
                for (int mq = 0; mq < 8; mq++) {
                    const float* eb = s_conv + a0 * H + mq * 4;
                    float4 e0 = *(const float4*)(eb);
                    float4 e1 = *(const float4*)(eb + H);
                    float4 e2 = *(const float4*)(eb + 2 * H);
                    float4 e3 = *(const float4*)(eb + 3 * H);
                    float4 qx = s_Wo14[(mq * 2 + 0) * 16 + lh];
                    float4 qy = s_Wo14[(mq * 2 + 1) * 16 + lh];
#define ACC4(C, E) \
                    C.x = fmaf(E.x, qx.x, fmaf(E.y, qx.y, fmaf(E.z, qx.z, fmaf(E.w, qx.w, C.x)))); \
                    C.y = fmaf(E.x, qy.x, fmaf(E.y, qy.y, fmaf(E.z, qy.z, fmaf(E.w, qy.w, C.y))));
                    ACC4(c0, e0) ACC4(c1, e1) ACC4(c2, e2) ACC4(c3, e3)
#undef ACC4
                }
                c0.x = tanh_fast(c0.x); c0.y = tanh_fast(c0.y);
                c1.x = tanh_fast(c1.x); c1.y = tanh_fast(c1.y);
                c2.x = tanh_fast(c2.x); c2.y = tanh_fast(c2.y);
                c3.x = tanh_fast(c3.x); c3.y = tanh_fast(c3.y);

                __syncwarp();
                *(float2*)&s_conv[(a0 + 0) * H + 2 * lh] = c0;
                *(float2*)&s_conv[(a0 + 1) * H + 2 * lh] = c1;
                *(float2*)&s_conv[(a0 + 2) * H + 2 * lh] = c2;
                *(float2*)&s_conv[(a0 + 3) * H + 2 * lh] = c3;
                __syncwarp();

                float2 d0 = b2v, d1 = b2v, d2 = b2v, d3 = b2v;
#pragma unroll
                for (int mq = 0; mq < 8; mq++) {
                    const float* eb = s_conv + a0 * H + mq * 4;
                    float4 e0 = *(const float4*)(eb);
                    float4 e1 = *(const float4*)(eb + H);
                    float4 e2 = *(const float4*)(eb + 2 * H);
                    float4 e3 = *(const float4*)(eb + 3 * H);
                    float4 qx = s_Wo24[(mq * 2 + 0) * 16 + lh];
                    float4 qy = s_Wo24[(mq * 2 + 1) * 16 + lh];
#define ACC4(C, E) \
                    C.x = fmaf(E.x, qx.x, fmaf(E.y, qx.y, fmaf(E.z, qx.z, fmaf(E.w, qx.w, C.x)))); \
                    C.y = fmaf(E.x, qy.x, fmaf(E.y, qy.y, fmaf(E.z, qy.z, fmaf(E.w, qy.w, C.y))));
                    ACC4(d0, e0) ACC4(d1, e1) ACC4(d2, e2) ACC4(d3, e3)
#undef ACC4
                }

#pragma unroll
                for (int r = 0; r < 4; r++) {
                    int a = a0 + r;
                    if (a < NATOMS) {
                        float2 dd = (r == 0) ? d0 : (r == 1) ? d1 : (r == 2) ? d2 : d3;
                        float2 old = *(const float2*)&s_emb[a * H + 2 * lh];
                        float nex = old.x + dd.x;
                        float ney = old.y + dd.y;
                        if (l < NCONV - 1) {
                            *(float2*)&s_emb[a * H + 2 * lh] = make_float2(nex, ney);
                        } else {
                            pool.x += fmaxf(nex, 0.f);
                            pool.y += fmaxf(ney, 0.f);
                        }
                    }
                }
            }
        }
        __syncthreads();
    }

    // ---- fused pool + final linear ----
    pool.x += __shfl_xor_sync(FULL, pool.x, 16);
    pool.y += __shfl_xor_sync(FULL, pool.y, 16);
    if (lane < 16) {
        s_warp[w * H + 2 * lane]     = pool.x;
        s_warp[w * H + 2 * lane + 1] = pool.y;
    }
    __syncthreads();
    if (w == 0) {
        float p = 0.f;
#pragma unroll
        for (int i = 0; i < 8; i++) p += s_warp[i * H + lane];
        s_pooled[lane] = p * (1.0f / (float)NATOMS);
        __syncwarp();
        if (lane < GDIM) {
            float o = __ldg(&bg[lane]);
#pragma unroll
            for (int k = 0; k < H; k++)
                o = fmaf(s_pooled[k], __ldg(&Wg[lane * H + k]), o);
            out[g * GDIM + lane] = o;
        }
    }
}

// ============================================================
extern "C" void kernel_launch(void* const* d_in, const int* in_sizes, int n_in,
                              void* d_out, int out_size) {
    const float* data      = (const float*)d_in[0];
    const float* emb_table = (const float*)d_in[1];
    const float* W_init    = (const float*)d_in[2];
    const float* Wf1       = (const float*)d_in[3];
    const float* bf1       = (const float*)d_in[4];
    const float* Wf2       = (const float*)d_in[5];
    const float* bf2       = (const float*)d_in[6];
    const float* coef      = (const float*)d_in[7];
    const float* Wo1       = (const float*)d_in[8];
    const float* bo1       = (const float*)d_in[9];
    const float* Wo2       = (const float*)d_in[10];
    const float* bo2       = (const float*)d_in[11];
    const float* Wg        = (const float*)d_in[12];
    const float* bg        = (const float*)d_in[13];
    float* out = (float*)d_out;

    static int smem_set = 0;
    if (!smem_set) {
        cudaFuncSetAttribute(fused_kernel,
                             cudaFuncAttributeMaxDynamicSharedMemorySize,
                             SMEM_BYTES);
        smem_set = 1;
    }

    build_raw_kernel<<<dim3((TBL + 1 + 7) / 8, NCONV), 256>>>(Wf1, bf1, Wf2, bf2);
    pack_edges_kernel<<<(NN * DEG + 255) / 256, 256>>>(data);
    pack_table_kernel<<<(NCONV * TBL * HP + 255) / 256, 256>>>();
    fused_kernel<<<NGRAPH, 256, SMEM_BYTES>>>(emb_table, W_init, coef,
                                              Wo1, bo1, Wo2, bo2, Wg, bg, out);
}